// round 5
// baseline (speedup 1.0000x reference)
#include <cuda_runtime.h>
#include <cstdint>

// Problem constants (fixed by the dataset problem)
#define D_DIM   2048
#define E_DIM   8
#define TPG     4          // tokens per warp-group task (4 tok x 8 exp = 32 lanes)
#define WARPS_PER_BLOCK 16
#define THREADS_PER_BLOCK (WARPS_PER_BLOCK*32)
#define GRID_BLOCKS 148

__device__ float g_acc[2];          // [0]=entropy sum, [1]=expected_steps sum
__device__ unsigned int g_counter;  // block completion counter

// ---------------------------------------------------------------------------
// Threefry-2x32 (20 rounds) — matches jax._src.prng exactly.
// ---------------------------------------------------------------------------
__device__ __forceinline__ uint32_t rotl32(uint32_t v, int r) {
    return (v << r) | (v >> (32 - r));
}

__device__ __forceinline__ void threefry2x32(uint32_t k0, uint32_t k1,
                                             uint32_t x0, uint32_t x1,
                                             uint32_t& o0, uint32_t& o1) {
    uint32_t ks2 = k0 ^ k1 ^ 0x1BD11BDAu;
    x0 += k0; x1 += k1;
#define TFR(r) { x0 += x1; x1 = rotl32(x1, r); x1 ^= x0; }
    TFR(13) TFR(15) TFR(26) TFR(6)   x0 += k1;  x1 += ks2 + 1u;
    TFR(17) TFR(29) TFR(16) TFR(24)  x0 += ks2; x1 += k0  + 2u;
    TFR(13) TFR(15) TFR(26) TFR(6)   x0 += k0;  x1 += k1  + 3u;
    TFR(17) TFR(29) TFR(16) TFR(24)  x0 += k1;  x1 += ks2 + 4u;
    TFR(13) TFR(15) TFR(26) TFR(6)   x0 += ks2; x1 += k0  + 5u;
#undef TFR
    o0 = x0; o1 = x1;
}

// Partitionable threefry random_bits (JAX >= 0.4.27 default):
//   per element j: (x0, x1) = (0, j); bits = out0 ^ out1
// Uniform [0,1): bitcast((bits>>9)|0x3f800000) - 1
__device__ __forceinline__ float jax_rand_f01(uint32_t k1, uint32_t j) {
    uint32_t o0, o1;
    threefry2x32(0u, k1, 0u, j, o0, o1);
    uint32_t bits = o0 ^ o1;
    return __uint_as_float((bits >> 9) | 0x3f800000u) - 1.0f;
}

// ---------------------------------------------------------------------------
// Single fused kernel: persistent blocks, W cached in smem once per block,
// per-warp group loop, counter-based last-block finalize (+ state reset so
// the kernel is graph-replayable / deterministic).
// ---------------------------------------------------------------------------
__global__ void __launch_bounds__(THREADS_PER_BLOCK)
router_kernel(const float* __restrict__ x,
              const float* __restrict__ W,
              const float* __restrict__ b,
              float* __restrict__ out,
              int n_groups, int ntot, float inv_m) {
    extern __shared__ float4 sW[];            // E_DIM * 512 float4 = 64 KB
    __shared__ float sacc[2];
    __shared__ bool  is_last;

    const int tid  = threadIdx.x;
    const int lane = tid & 31;
    const int wid  = tid >> 5;
    const int bid  = blockIdx.x;

    if (tid == 0) { sacc[0] = 0.0f; sacc[1] = 0.0f; }

    // Per-block group range (balanced: first `rem` blocks get one extra)
    const int nper = n_groups / gridDim.x;
    const int rem  = n_groups - nper * gridDim.x;
    const int nb   = nper + (bid < rem ? 1 : 0);
    const int g0   = bid * nper + min(bid, rem);

    // Cooperative W load into shared (row-major (8,2048) == flat float4[4096])
    if (nb > 0) {
        const float4* Wg = reinterpret_cast<const float4*>(W);
#pragma unroll
        for (int i = tid; i < E_DIM * (D_DIM / 4); i += THREADS_PER_BLOCK)
            sW[i] = Wg[i];
    }
    __syncthreads();

    const float bias = __ldg(&b[lane & 7]);

    float ent_blk = 0.0f, step_blk = 0.0f;   // per-thread partials (lane 0 used)

    for (int gi = wid; gi < nb; gi += WARPS_PER_BLOCK) {
        const int group = g0 + gi;
        const int t0 = group * TPG;

        // Accumulators: v[t*8+e]
        float v[TPG * E_DIM];
#pragma unroll
        for (int i = 0; i < TPG * E_DIM; i++) v[i] = 0.0f;

        const float4* xr = reinterpret_cast<const float4*>(x) + (size_t)t0 * (D_DIM / 4);

#pragma unroll
        for (int it = 0; it < (D_DIM / 4) / 32; it++) {      // 16 iterations
            const int idx = it * 32 + lane;
            float4 xa = xr[idx];
            float4 xb = xr[512 + idx];
            float4 xc = xr[1024 + idx];
            float4 xd = xr[1536 + idx];
#pragma unroll
            for (int e = 0; e < E_DIM; e++) {
                float4 w = sW[e * 512 + idx];
                v[0 * 8 + e] += xa.x * w.x + xa.y * w.y + xa.z * w.z + xa.w * w.w;
                v[1 * 8 + e] += xb.x * w.x + xb.y * w.y + xb.z * w.z + xb.w * w.w;
                v[2 * 8 + e] += xc.x * w.x + xc.y * w.y + xc.z * w.z + xc.w * w.w;
                v[3 * 8 + e] += xd.x * w.x + xd.y * w.y + xd.z * w.z + xd.w * w.w;
            }
        }

        // Butterfly transpose-reduce: lane l ends with total for value index l.
#pragma unroll
        for (int bshift = 4; bshift >= 0; bshift--) {
            const int mk = 1 << bshift;
            const bool hi = (lane >> bshift) & 1;
#pragma unroll
            for (int jj = 0; jj < 32; jj++) {
                if (jj < mk) {
                    float a = v[jj], c = v[jj + mk];
                    float keep = hi ? c : a;
                    float send = hi ? a : c;
                    v[jj] = keep + __shfl_xor_sync(0xffffffffu, send, mk);
                }
            }
        }

        const int e  = lane & 7;
        const int tl = lane >> 3;
        const int t  = t0 + tl;

        float z = v[0] + bias;                // logits

        // numerical stabilization: subtract per-token max (8-lane segments)
        float m = z;
        m = fmaxf(m, __shfl_xor_sync(0xffffffffu, m, 1));
        m = fmaxf(m, __shfl_xor_sync(0xffffffffu, m, 2));
        m = fmaxf(m, __shfl_xor_sync(0xffffffffu, m, 4));
        z -= m;

        // training noise: normal(key(1)) * 0.05
        const uint32_t j = (uint32_t)t * 8u + (uint32_t)e;
        {
            float f01 = jax_rand_f01(1u, j);
            const float LO = -0.99999994f;                    // nextafter(-1,0)
            float u = f01 * (1.0f - LO) + LO;
            u = fmaxf(u, LO);
            float nrm = 1.41421356237f * erfinvf(u);
            z = z + nrm * 0.05f;
        }
        z = fminf(fmaxf(z, -50.0f), 50.0f);                   // clip

        // inv_t = 1/(1+1e-8) rounds to 1.0f in fp32 — omit the multiply
        float zs = z;

        // soft_probs = softmax(zs) per token
        float m2 = zs;
        m2 = fmaxf(m2, __shfl_xor_sync(0xffffffffu, m2, 1));
        m2 = fmaxf(m2, __shfl_xor_sync(0xffffffffu, m2, 2));
        m2 = fmaxf(m2, __shfl_xor_sync(0xffffffffu, m2, 4));
        float p = expf(zs - m2);
        float s = p;
        s += __shfl_xor_sync(0xffffffffu, s, 1);
        s += __shfl_xor_sync(0xffffffffu, s, 2);
        s += __shfl_xor_sync(0xffffffffu, s, 4);
        float soft = p / s;

        // entropy & expected steps contributions (per lane, then segment sums)
        float ent_tok  = -soft * logf(soft + 1e-8f);
        float step_tok = soft * (float)e;
        ent_tok  += __shfl_xor_sync(0xffffffffu, ent_tok, 1);
        ent_tok  += __shfl_xor_sync(0xffffffffu, ent_tok, 2);
        ent_tok  += __shfl_xor_sync(0xffffffffu, ent_tok, 4);
        step_tok += __shfl_xor_sync(0xffffffffu, step_tok, 1);
        step_tok += __shfl_xor_sync(0xffffffffu, step_tok, 2);
        step_tok += __shfl_xor_sync(0xffffffffu, step_tok, 4);

        // gumbel noise from key(2), scaled by 0.5
        float u2 = jax_rand_f01(2u, j);
        float g  = -logf(-logf(u2 + 1e-8f) + 1e-8f) * 0.5f;
        float zg = z + g;
        float m3 = zg;
        m3 = fmaxf(m3, __shfl_xor_sync(0xffffffffu, m3, 1));
        m3 = fmaxf(m3, __shfl_xor_sync(0xffffffffu, m3, 2));
        m3 = fmaxf(m3, __shfl_xor_sync(0xffffffffu, m3, 4));
        float pg = expf(zg - m3);
        float sg = pg;
        sg += __shfl_xor_sync(0xffffffffu, sg, 1);
        sg += __shfl_xor_sync(0xffffffffu, sg, 2);
        sg += __shfl_xor_sync(0xffffffffu, sg, 4);
        float rw = pg / sg;

        // coalesced stores: value index within warp == lane
        out[(size_t)t0 * 8 + lane]            = rw;
        out[(size_t)ntot + 2 + t0 * 8 + lane] = soft;

        // warp totals over the 4 tokens (segment-replicated; xor 8,16 sums
        // each token exactly once)
        float ew = ent_tok;
        ew += __shfl_xor_sync(0xffffffffu, ew, 8);
        ew += __shfl_xor_sync(0xffffffffu, ew, 16);
        float sw2 = step_tok;
        sw2 += __shfl_xor_sync(0xffffffffu, sw2, 8);
        sw2 += __shfl_xor_sync(0xffffffffu, sw2, 16);
        ent_blk  += ew;    // only lane 0's copy is consumed below
        step_blk += sw2;
    }

    if (lane == 0 && ent_blk != 0.0f) {
        atomicAdd(&sacc[0], ent_blk);
        atomicAdd(&sacc[1], step_blk);
    }
    // also handle the (possible) case ent_blk==0 with work done: cheap to just
    // always add from lane 0 if this warp processed anything
    if (lane == 0 && ent_blk == 0.0f && step_blk != 0.0f)
        atomicAdd(&sacc[1], step_blk);
    __syncthreads();

    // Block -> global accumulation, then last block finalizes & resets state.
    if (tid == 0) {
        atomicAdd(&g_acc[0], sacc[0]);
        atomicAdd(&g_acc[1], sacc[1]);
        __threadfence();
        unsigned int v = atomicAdd(&g_counter, 1u);
        is_last = (v == gridDim.x - 1);
    }
    __syncthreads();

    if (is_last && tid == 0) {
        float e0 = atomicAdd(&g_acc[0], 0.0f);   // fenced reads via atomic
        float e1 = atomicAdd(&g_acc[1], 0.0f);
        float ent = e0 * inv_m;
        ent = fminf(fmaxf(ent, 0.0f), 20.0f);
        out[ntot]     = ent;
        out[ntot + 1] = e1 * inv_m;
        // reset for next graph replay (kernel completion publishes these)
        g_acc[0] = 0.0f;
        g_acc[1] = 0.0f;
        __threadfence();
        g_counter = 0u;
    }
}

// ---------------------------------------------------------------------------
extern "C" void kernel_launch(void* const* d_in, const int* in_sizes, int n_in,
                              void* d_out, int out_size) {
    const float* x = (const float*)d_in[0];
    const float* W = (const float*)d_in[1];
    const float* b = (const float*)d_in[2];
    float* out = (float*)d_out;

    const int E = in_sizes[2];                 // 8
    const int D = in_sizes[1] / E;             // 2048
    const int M = in_sizes[0] / D;             // 16384 tokens
    const int ntot = M * E;                    // 131072
    const int n_groups = M / TPG;              // 4096

    const int smem = E_DIM * (D_DIM / 4) * sizeof(float4);   // 64 KB
    cudaFuncSetAttribute(router_kernel,
                         cudaFuncAttributeMaxDynamicSharedMemorySize, smem);

    router_kernel<<<GRID_BLOCKS, THREADS_PER_BLOCK, smem>>>(
        x, W, b, out, n_groups, ntot, 1.0f / (float)M);
}

// round 8
// speedup vs baseline: 3.8586x; 3.8586x over previous
#include <cuda_runtime.h>
#include <cstdint>

// Problem constants (fixed by the dataset problem)
#define D_DIM   2048
#define E_DIM   8
#define TPG     4          // tokens per warp (4 tok x 8 exp = 32 lanes)
#define WARPS_PER_BLOCK 8
#define THREADS_PER_BLOCK (WARPS_PER_BLOCK*32)

__device__ float g_acc[2];          // [0]=entropy sum, [1]=expected_steps sum
__device__ unsigned int g_counter;  // block completion counter

// ---------------------------------------------------------------------------
// Threefry-2x32 (20 rounds) — matches jax._src.prng exactly.
// ---------------------------------------------------------------------------
__device__ __forceinline__ uint32_t rotl32(uint32_t v, int r) {
    return (v << r) | (v >> (32 - r));
}

__device__ __forceinline__ void threefry2x32(uint32_t k0, uint32_t k1,
                                             uint32_t x0, uint32_t x1,
                                             uint32_t& o0, uint32_t& o1) {
    uint32_t ks2 = k0 ^ k1 ^ 0x1BD11BDAu;
    x0 += k0; x1 += k1;
#define TFR(r) { x0 += x1; x1 = rotl32(x1, r); x1 ^= x0; }
    TFR(13) TFR(15) TFR(26) TFR(6)   x0 += k1;  x1 += ks2 + 1u;
    TFR(17) TFR(29) TFR(16) TFR(24)  x0 += ks2; x1 += k0  + 2u;
    TFR(13) TFR(15) TFR(26) TFR(6)   x0 += k0;  x1 += k1  + 3u;
    TFR(17) TFR(29) TFR(16) TFR(24)  x0 += k1;  x1 += ks2 + 4u;
    TFR(13) TFR(15) TFR(26) TFR(6)   x0 += ks2; x1 += k0  + 5u;
#undef TFR
    o0 = x0; o1 = x1;
}

// Partitionable threefry random_bits (JAX >= 0.4.27 default):
//   per element j: (x0, x1) = (0, j); bits = out0 ^ out1
// Uniform [0,1): bitcast((bits>>9)|0x3f800000) - 1
__device__ __forceinline__ float jax_rand_f01(uint32_t k1, uint32_t j) {
    uint32_t o0, o1;
    threefry2x32(0u, k1, 0u, j, o0, o1);
    uint32_t bits = o0 ^ o1;
    return __uint_as_float((bits >> 9) | 0x3f800000u) - 1.0f;
}

// ---------------------------------------------------------------------------
// Fused kernel: GEMM (x @ W^T + b) + router epilogue + last-block finalize.
// One warp per 4-token group. W cached in shared per block.
// ---------------------------------------------------------------------------
__global__ void __launch_bounds__(THREADS_PER_BLOCK)
router_kernel(const float* __restrict__ x,
              const float* __restrict__ W,
              const float* __restrict__ b,
              float* __restrict__ out,
              int ntot, float inv_m) {
    extern __shared__ float4 sW[];            // E_DIM * 512 float4 = 64 KB
    __shared__ float sacc[2];
    __shared__ bool  is_last;

    const int tid  = threadIdx.x;
    const int lane = tid & 31;
    const int wid  = tid >> 5;

    if (tid == 0) { sacc[0] = 0.0f; sacc[1] = 0.0f; }

    // Cooperative W load into shared (row-major (8,2048) == flat float4[4096])
    const float4* Wg = reinterpret_cast<const float4*>(W);
#pragma unroll
    for (int i = tid; i < E_DIM * (D_DIM / 4); i += THREADS_PER_BLOCK)
        sW[i] = Wg[i];
    __syncthreads();

    const int group = blockIdx.x * WARPS_PER_BLOCK + wid;
    const int t0 = group * TPG;

    // Accumulators: v[t*8+e]
    float v[TPG * E_DIM];
#pragma unroll
    for (int i = 0; i < TPG * E_DIM; i++) v[i] = 0.0f;

    const float4* xr = reinterpret_cast<const float4*>(x) + (size_t)t0 * (D_DIM / 4);

    // Software-pipelined K loop: prefetch next iteration's 4 x-tiles while
    // computing the current one (keeps >= 8 float4 loads in flight per warp).
    float4 xa = xr[lane];
    float4 xb = xr[512 + lane];
    float4 xc = xr[1024 + lane];
    float4 xd = xr[1536 + lane];

#pragma unroll
    for (int it = 0; it < (D_DIM / 4) / 32; it++) {          // 16 iterations
        const int idx = it * 32 + lane;
        float4 na, nb2, nc, nd;
        if (it < (D_DIM / 4) / 32 - 1) {
            const int nidx = idx + 32;
            na  = xr[nidx];
            nb2 = xr[512 + nidx];
            nc  = xr[1024 + nidx];
            nd  = xr[1536 + nidx];
        }
#pragma unroll
        for (int e = 0; e < E_DIM; e++) {
            float4 w = sW[e * 512 + idx];
            v[0 * 8 + e] += xa.x * w.x + xa.y * w.y + xa.z * w.z + xa.w * w.w;
            v[1 * 8 + e] += xb.x * w.x + xb.y * w.y + xb.z * w.z + xb.w * w.w;
            v[2 * 8 + e] += xc.x * w.x + xc.y * w.y + xc.z * w.z + xc.w * w.w;
            v[3 * 8 + e] += xd.x * w.x + xd.y * w.y + xd.z * w.z + xd.w * w.w;
        }
        xa = na; xb = nb2; xc = nc; xd = nd;
    }

    // Butterfly transpose-reduce: lane l ends with total for value index l.
#pragma unroll
    for (int bshift = 4; bshift >= 0; bshift--) {
        const int mk = 1 << bshift;
        const bool hi = (lane >> bshift) & 1;
#pragma unroll
        for (int jj = 0; jj < 32; jj++) {
            if (jj < mk) {
                float a = v[jj], c = v[jj + mk];
                float keep = hi ? c : a;
                float send = hi ? a : c;
                v[jj] = keep + __shfl_xor_sync(0xffffffffu, send, mk);
            }
        }
    }

    const int e  = lane & 7;
    const int tl = lane >> 3;
    const int t  = t0 + tl;

    float z = v[0] + __ldg(&b[e]);        // logits

    // numerical stabilization: subtract per-token max (8-lane segments)
    float m = z;
    m = fmaxf(m, __shfl_xor_sync(0xffffffffu, m, 1));
    m = fmaxf(m, __shfl_xor_sync(0xffffffffu, m, 2));
    m = fmaxf(m, __shfl_xor_sync(0xffffffffu, m, 4));
    z -= m;

    // training noise: normal(key(1)) * 0.05
    const uint32_t j = (uint32_t)t * 8u + (uint32_t)e;
    {
        float f01 = jax_rand_f01(1u, j);
        const float LO = -0.99999994f;                    // nextafter(-1,0)
        float u = f01 * (1.0f - LO) + LO;
        u = fmaxf(u, LO);
        float nrm = 1.41421356237f * erfinvf(u);
        z = z + nrm * 0.05f;
    }
    z = fminf(fmaxf(z, -50.0f), 50.0f);                   // clip

    // inv_t = 1/(1+1e-8) rounds to 1.0f in fp32 — omit the multiply
    float zs = z;

    // soft_probs = softmax(zs) per token
    float m2 = zs;
    m2 = fmaxf(m2, __shfl_xor_sync(0xffffffffu, m2, 1));
    m2 = fmaxf(m2, __shfl_xor_sync(0xffffffffu, m2, 2));
    m2 = fmaxf(m2, __shfl_xor_sync(0xffffffffu, m2, 4));
    float p = expf(zs - m2);
    float s = p;
    s += __shfl_xor_sync(0xffffffffu, s, 1);
    s += __shfl_xor_sync(0xffffffffu, s, 2);
    s += __shfl_xor_sync(0xffffffffu, s, 4);
    float soft = p / s;

    // entropy & expected steps contributions (per lane, then segment sums)
    float ent_tok  = -soft * logf(soft + 1e-8f);
    float step_tok = soft * (float)e;
    ent_tok  += __shfl_xor_sync(0xffffffffu, ent_tok, 1);
    ent_tok  += __shfl_xor_sync(0xffffffffu, ent_tok, 2);
    ent_tok  += __shfl_xor_sync(0xffffffffu, ent_tok, 4);
    step_tok += __shfl_xor_sync(0xffffffffu, step_tok, 1);
    step_tok += __shfl_xor_sync(0xffffffffu, step_tok, 2);
    step_tok += __shfl_xor_sync(0xffffffffu, step_tok, 4);

    // gumbel noise from key(2), scaled by 0.5
    float u2 = jax_rand_f01(2u, j);
    float g  = -logf(-logf(u2 + 1e-8f) + 1e-8f) * 0.5f;
    float zg = z + g;
    float m3 = zg;
    m3 = fmaxf(m3, __shfl_xor_sync(0xffffffffu, m3, 1));
    m3 = fmaxf(m3, __shfl_xor_sync(0xffffffffu, m3, 2));
    m3 = fmaxf(m3, __shfl_xor_sync(0xffffffffu, m3, 4));
    float pg = expf(zg - m3);
    float sg = pg;
    sg += __shfl_xor_sync(0xffffffffu, sg, 1);
    sg += __shfl_xor_sync(0xffffffffu, sg, 2);
    sg += __shfl_xor_sync(0xffffffffu, sg, 4);
    float rw = pg / sg;

    // coalesced stores: value index within warp == lane
    out[(size_t)t0 * 8 + lane]            = rw;
    out[(size_t)ntot + 2 + t0 * 8 + lane] = soft;

    // warp totals over the 4 tokens (segment-replicated; xor 8,16 sums
    // each token exactly once)
    float ew = ent_tok;
    ew += __shfl_xor_sync(0xffffffffu, ew, 8);
    ew += __shfl_xor_sync(0xffffffffu, ew, 16);
    float sw2 = step_tok;
    sw2 += __shfl_xor_sync(0xffffffffu, sw2, 8);
    sw2 += __shfl_xor_sync(0xffffffffu, sw2, 16);
    if (lane == 0) {
        atomicAdd(&sacc[0], ew);
        atomicAdd(&sacc[1], sw2);
    }
    __syncthreads();

    // Block -> global accumulation, then last block finalizes & resets state.
    if (tid == 0) {
        atomicAdd(&g_acc[0], sacc[0]);
        atomicAdd(&g_acc[1], sacc[1]);
        __threadfence();
        unsigned int cv = atomicAdd(&g_counter, 1u);
        is_last = (cv == gridDim.x - 1);
    }
    __syncthreads();

    if (is_last && tid == 0) {
        float e0 = atomicAdd(&g_acc[0], 0.0f);   // fenced reads via atomic
        float e1 = atomicAdd(&g_acc[1], 0.0f);
        float ent = e0 * inv_m;
        ent = fminf(fmaxf(ent, 0.0f), 20.0f);
        out[ntot]     = ent;
        out[ntot + 1] = e1 * inv_m;
        // reset for next graph replay
        g_acc[0] = 0.0f;
        g_acc[1] = 0.0f;
        __threadfence();
        g_counter = 0u;
    }
}

// ---------------------------------------------------------------------------
extern "C" void kernel_launch(void* const* d_in, const int* in_sizes, int n_in,
                              void* d_out, int out_size) {
    const float* x = (const float*)d_in[0];
    const float* W = (const float*)d_in[1];
    const float* b = (const float*)d_in[2];
    float* out = (float*)d_out;

    const int E = in_sizes[2];                 // 8
    const int D = in_sizes[1] / E;             // 2048
    const int M = in_sizes[0] / D;             // 16384 tokens
    const int ntot = M * E;                    // 131072
    const int n_groups = M / TPG;              // 4096
    const int blocks = n_groups / WARPS_PER_BLOCK;           // 512

    const int smem = E_DIM * (D_DIM / 4) * sizeof(float4);   // 64 KB
    cudaFuncSetAttribute(router_kernel,
                         cudaFuncAttributeMaxDynamicSharedMemorySize, smem);

    router_kernel<<<blocks, THREADS_PER_BLOCK, smem>>>(
        x, W, b, out, ntot, 1.0f / (float)M);
}